// round 9
// baseline (speedup 1.0000x reference)
#include <cuda_runtime.h>
#include <cuda_bf16.h>

// Problem constants
#define HH 64
#define WW 64
#define CIN 256
#define COUT 256
#define BB 8
#define KKT 9
#define HWSZ 4096            // H*W
#define KTOT 2304            // 9*256

typedef unsigned long long ull;

// ---------------- scratch (device globals: no allocation allowed) ----------
__device__ float  g_xn[BB * HWSZ * CIN];     // x in NHWC (33.5 MB)
__device__ float  g_wT[KTOT * COUT];         // W^T [k][oc], k=tap*256+c
__device__ float  g_wB[KTOT * 32];           // offset/mod weights [k][32] (27 used)
__device__ short4 g_sxy[BB * KKT * HWSZ];    // clamped corner coords
__device__ float4 g_swt[BB * KKT * HWSZ];    // bilinear*mask*valid weights
// im2col A, tiled: [(bt*32+mchunk)*16+cc][16 k][128 m]  (302 MB)
__device__ float  g_A[(size_t)BB * KKT * CIN * HWSZ];

// ---------------- helpers ---------------------------------------------------
__device__ __forceinline__ ull fma2(ull a, ull b, ull c) {
    ull d;
    asm("fma.rn.f32x2 %0, %1, %2, %3;" : "=l"(d) : "l"(a), "l"(b), "l"(c));
    return d;
}
__device__ __forceinline__ float2 upk2(ull v) {
    float2 r;
    asm("mov.b64 {%0, %1}, %2;" : "=f"(r.x), "=f"(r.y) : "l"(v));
    return r;
}
__device__ __forceinline__ ull dup2(float v) {
    ull r;
    asm("mov.b64 %0, {%1, %1};" : "=l"(r) : "f"(v));
    return r;
}
__device__ __forceinline__ void cpa16(unsigned int s, const void* g) {
    asm volatile("cp.async.cg.shared.global [%0], [%1], 16;" :: "r"(s), "l"(g));
}

// ---------------- kernel: NCHW -> NHWC transpose of x ----------------------
__global__ void k_transpose(const float* __restrict__ x) {
    __shared__ float tile[32][33];
    int b  = blockIdx.z;
    int p0 = blockIdx.x * 32;
    int c0 = blockIdx.y * 32;
    const float* xb = x    + (size_t)b * (CIN * HWSZ);
    float*       ob = g_xn + (size_t)b * (HWSZ * CIN);
    int tx = threadIdx.x, ty = threadIdx.y;
#pragma unroll
    for (int i = 0; i < 4; i++)
        tile[ty + i * 8][tx] = xb[(size_t)(c0 + ty + i * 8) * HWSZ + p0 + tx];
    __syncthreads();
#pragma unroll
    for (int i = 0; i < 4; i++)
        ob[(size_t)(p0 + ty + i * 8) * CIN + c0 + tx] = tile[tx][ty + i * 8];
}

// ---------------- kernel: transpose reg_w to [k][oc] -----------------------
__global__ void k_wt(const float* __restrict__ reg_w) {
    int idx = blockIdx.x * 256 + threadIdx.x;
    if (idx >= KTOT * COUT) return;
    int oc  = idx & 255;
    int k   = idx >> 8;
    int tap = k >> 8;
    int c   = k & 255;
    g_wT[idx] = reg_w[(size_t)(oc * CIN + c) * KKT + tap];
}

// ---------------- kernel: build g_wB [k][32] (pad to 32, zeros beyond 27) --
__global__ void k_wom(const float* __restrict__ ow, const float* __restrict__ mw) {
    int idx = blockIdx.x * 256 + threadIdx.x;
    if (idx >= KTOT * 32) return;
    int n   = idx & 31;
    int k   = idx >> 5;
    int tap = k >> 8;
    int c   = k & 255;
    float v = 0.f;
    if (n < 18)      v = ow[(size_t)(n * CIN + c) * KKT + tap];
    else if (n < 27) v = mw[(size_t)((n - 18) * CIN + c) * KKT + tap];
    g_wB[idx] = v;
}

// ---------------- kernel: offset/mod conv as register-blocked GEMM ---------
// grid 512 = (b, row). Tile M=64, N=32, K=2304 as 72 stages of 32.
// 128 threads: ty=tid>>3 (16, x4 m via 2 f32x2), tx=tid&7 (8, x4 n).
// A staged LDG->regs->swizzled STS; stage s+1 LDGs issued before compute of s
// (~700-cycle prefetch distance hides L2 latency at low occupancy).
__global__ void __launch_bounds__(128) k_offmod(const float* __restrict__ off_b,
                                                const float* __restrict__ mod_b) {
    __shared__ __align__(16) float As[32 * 64];   // [k][m], XOR-swizzled cols (8 KB)
    __shared__ __align__(16) float Bs[32 * 32];   // [k][n] (4 KB)
    __shared__ float red[64][28];

    int blk  = blockIdx.x;
    int b    = blk >> 6;
    int y    = blk & 63;            // image row = M tile
    int pos0 = y << 6;
    int tid  = threadIdx.x;
    int tx   = tid & 7;
    int ty   = tid >> 3;
    int px   = tid >> 2;            // A-fill pixel 0..31 (+32)
    int cs2  = tid & 3;             // A-fill c4 subgroup
    int rB   = tid >> 3;            // B-fill row (and +16)
    int nB   = (tid & 7) * 4;

    const float4* X4 = (const float4*)g_xn;

    ull acc[2][4];
#pragma unroll
    for (int i = 0; i < 2; i++)
#pragma unroll
        for (int j = 0; j < 4; j++) acc[i][j] = 0ULL;

    float4 ra[2][2], rb[2];

#define LOADSTAGE(s)                                                             \
    {                                                                            \
        int tap = (s) >> 3, cc = (s) & 7;                                        \
        int dy = tap / 3 - 1, dx = tap % 3 - 1;                                  \
        int y2 = y + dy;                                                         \
        bool rowok = (y2 >= 0) && (y2 < HH);                                     \
        _Pragma("unroll")                                                        \
        for (int it = 0; it < 2; it++) {                                         \
            int m = px + it * 32;                                                \
            int x2 = m + dx;                                                     \
            bool valid = rowok && (x2 >= 0) && (x2 < WW);                        \
            const float4* p = X4 + (size_t)(b * HWSZ + y2 * WW + x2) * 64        \
                                  + cc * 8 + cs2;                                \
            ra[it][0] = valid ? p[0] : make_float4(0.f, 0.f, 0.f, 0.f);          \
            ra[it][1] = valid ? p[4] : make_float4(0.f, 0.f, 0.f, 0.f);          \
        }                                                                        \
        rb[0] = *(const float4*)(g_wB + ((size_t)(s) * 32 + rB) * 32 + nB);      \
        rb[1] = *(const float4*)(g_wB + ((size_t)(s) * 32 + rB + 16) * 32 + nB); \
    }

    LOADSTAGE(0);

    for (int s = 0; s < 72; s++) {
        __syncthreads();
        // STS staged regs: row kr = cs2*4 + 16h + e, col = m ^ (cs2<<3)
#pragma unroll
        for (int it = 0; it < 2; it++) {
            int col = (px + it * 32) ^ (cs2 << 3);
#pragma unroll
            for (int h = 0; h < 2; h++) {
                int kr = cs2 * 4 + h * 16;
                As[(kr + 0) * 64 + col] = (&ra[it][h].x)[0];
                As[(kr + 1) * 64 + col] = (&ra[it][h].x)[1];
                As[(kr + 2) * 64 + col] = (&ra[it][h].x)[2];
                As[(kr + 3) * 64 + col] = (&ra[it][h].x)[3];
            }
        }
        *(float4*)(Bs + rB * 32 + nB)        = rb[0];
        *(float4*)(Bs + (rB + 16) * 32 + nB) = rb[1];
        __syncthreads();
        if (s + 1 < 72) { LOADSTAGE(s + 1); }   // LDG in flight under compute
#pragma unroll
        for (int kk = 0; kk < 32; kk++) {
            ulonglong2 a2 = *(const ulonglong2*)&As[kk * 64 + ((ty * 4) ^ ((kk & 12) << 1))];
            float4 bv = *(const float4*)&Bs[kk * 32 + tx * 4];
            ull bd[4] = {dup2(bv.x), dup2(bv.y), dup2(bv.z), dup2(bv.w)};
#pragma unroll
            for (int j = 0; j < 4; j++) {
                acc[0][j] = fma2(a2.x, bd[j], acc[0][j]);
                acc[1][j] = fma2(a2.y, bd[j], acc[1][j]);
            }
        }
    }
#undef LOADSTAGE

    // transpose accs -> red[px][n]
    __syncthreads();
#pragma unroll
    for (int i = 0; i < 2; i++)
#pragma unroll
        for (int j = 0; j < 4; j++) {
            int n = tx * 4 + j;
            if (n < 27) {
                float2 v = upk2(acc[i][j]);
                red[ty * 4 + 2 * i][n]     = v.x;
                red[ty * 4 + 2 * i + 1][n] = v.y;
            }
        }
    __syncthreads();

    // prep: 576 (px, tap) items
    for (int w = tid; w < 64 * 9; w += 128) {
        int px_i = w / 9;
        int tap  = w - px_i * 9;
        int p2   = pos0 + px_i;
        float ay = red[px_i][2 * tap]     + off_b[2 * tap];
        float ax = red[px_i][2 * tap + 1] + off_b[2 * tap + 1];
        float am = red[px_i][18 + tap]    + mod_b[tap];
        float dyo = fminf(fmaxf(ay, -16.f), 16.f);
        float dxo = fminf(fmaxf(ax, -16.f), 16.f);
        float m   = 1.f / (1.f + __expf(-am));
        float py  = dyo + (float)(tap / 3) + (float)y    - 1.f;
        float px_ = dxo + (float)(tap % 3) + (float)px_i - 1.f;
        float y0f = floorf(py), x0f = floorf(px_);
        float ly  = py - y0f,   lx  = px_ - x0f;
        int y0 = (int)y0f, x0 = (int)x0f;
        bool vy0 = (y0 >= 0)     && (y0 < HH);
        bool vy1 = (y0 + 1 >= 0) && (y0 + 1 < HH);
        bool vx0 = (x0 >= 0)     && (x0 < WW);
        bool vx1 = (x0 + 1 >= 0) && (x0 + 1 < WW);
        float w00 = (1.f - ly) * (1.f - lx) * m * ((vy0 && vx0) ? 1.f : 0.f);
        float w01 = (1.f - ly) * lx         * m * ((vy0 && vx1) ? 1.f : 0.f);
        float w10 = ly * (1.f - lx)         * m * ((vy1 && vx0) ? 1.f : 0.f);
        float w11 = ly * lx                 * m * ((vy1 && vx1) ? 1.f : 0.f);
        int y0c = min(max(y0, 0), HH - 1);
        int y1c = min(max(y0 + 1, 0), HH - 1);
        int x0c = min(max(x0, 0), WW - 1);
        int x1c = min(max(x0 + 1, 0), WW - 1);
        int si = (b * 9 + tap) * HWSZ + p2;
        g_sxy[si] = make_short4((short)y0c, (short)y1c, (short)x0c, (short)x1c);
        g_swt[si] = make_float4(w00, w01, w10, w11);
    }
}

// ---------------- kernel: bilinear gather -> tiled im2col g_A --------------
// grid 1024 = (b, 32-px chunk); loops all 9 taps inside so consecutive taps'
// overlapping corner reads hit L1 (cross-tap reuse cuts L2 traffic).
__global__ void __launch_bounds__(256) k_gather() {
    __shared__ float sA[256 * 33];
    int blk = blockIdx.x;
    int b   = blk >> 7;
    int p32 = blk & 127;
    int pos0 = p32 << 5;
    int tid = threadIdx.x;
    int px  = tid >> 3;
    int cs  = tid & 7;
    int pb  = b * HWSZ;
    const float4* X4 = (const float4*)g_xn;

    int r8  = tid >> 5;
    int pxw = tid & 31;
    int mo  = (p32 & 3) << 5;

    for (int tap = 0; tap < 9; tap++) {
        int bt = b * 9 + tap;
        int si = bt * HWSZ + pos0 + px;
        short4 s  = g_sxy[si];
        float4 wc = g_swt[si];
        int a00 = (pb + s.x * WW + s.z) << 6;
        int a01 = (pb + s.x * WW + s.w) << 6;
        int a10 = (pb + s.y * WW + s.z) << 6;
        int a11 = (pb + s.y * WW + s.w) << 6;

#pragma unroll
        for (int i = 0; i < 8; i++) {
            int c4 = i * 8 + cs;
            float4 v0 = X4[a00 + c4];
            float4 v1 = X4[a01 + c4];
            float4 v2 = X4[a10 + c4];
            float4 v3 = X4[a11 + c4];
            int c = c4 * 4;
            sA[(c + 0) * 33 + px] = wc.x * v0.x + wc.y * v1.x + wc.z * v2.x + wc.w * v3.x;
            sA[(c + 1) * 33 + px] = wc.x * v0.y + wc.y * v1.y + wc.z * v2.y + wc.w * v3.y;
            sA[(c + 2) * 33 + px] = wc.x * v0.z + wc.y * v1.z + wc.z * v2.z + wc.w * v3.z;
            sA[(c + 3) * 33 + px] = wc.x * v0.w + wc.y * v1.w + wc.z * v2.w + wc.w * v3.w;
        }
        __syncthreads();

        size_t obase = ((size_t)bt * 32 + (p32 >> 2)) * 16 * 2048;
#pragma unroll 8
        for (int pass = 0; pass < 32; pass++) {
            int c = pass * 8 + r8;
            g_A[obase + (size_t)(c >> 4) * 2048 + (c & 15) * 128 + mo + pxw] = sA[c * 33 + pxw];
        }
        __syncthreads();
    }
}

// ---------------- kernel: main GEMM (cp.async, K-stage 32, double buffer) --
__global__ void __launch_bounds__(256, 2) k_main(float* __restrict__ out) {
    __shared__ __align__(16) float As[2][32 * 128];   // 32 KB
    __shared__ __align__(16) float Bs[2][32 * 128];   // 32 KB

    int mb   = blockIdx.x;           // b*32 + mchunk
    int b    = mb >> 5;
    int mch  = mb & 31;
    int pos0 = mch << 7;
    int noff = blockIdx.y << 7;

    int tid = threadIdx.x;
    int tx  = tid & 15;
    int ty  = tid >> 4;

    unsigned int sa0 = (unsigned int)__cvta_generic_to_shared(&As[0][0]);
    unsigned int sa1 = (unsigned int)__cvta_generic_to_shared(&As[1][0]);
    unsigned int sb0 = (unsigned int)__cvta_generic_to_shared(&Bs[0][0]);
    unsigned int sb1 = (unsigned int)__cvta_generic_to_shared(&Bs[1][0]);

    size_t Ab0 = ((size_t)b * 9 * 32 + mch) * 32768;   // float index
    int krB = tid >> 3, cBB = tid & 7;

    ull acc[4][8];
#pragma unroll
    for (int i = 0; i < 4; i++)
#pragma unroll
        for (int j = 0; j < 8; j++) acc[i][j] = 0ULL;

#define ISSUE(s, sa, sb)                                                            \
    {                                                                               \
        const float* ap = g_A + Ab0 + (size_t)((s) >> 3) * 1048576 + ((s) & 7) * 4096; \
        cpa16((sa) + (tid) * 16,          ap + (size_t)tid * 4);                    \
        cpa16((sa) + (tid + 256) * 16,    ap + (size_t)(tid + 256) * 4);            \
        cpa16((sa) + (tid + 512) * 16,    ap + (size_t)(tid + 512) * 4);            \
        cpa16((sa) + (tid + 768) * 16,    ap + (size_t)(tid + 768) * 4);            \
        const float* bp = g_wT + ((size_t)(s) * 32 + krB) * 256 + noff + cBB * 16;  \
        cpa16((sb) + (krB * 128 + cBB * 16) * 4,      bp);                          \
        cpa16((sb) + (krB * 128 + cBB * 16 + 4) * 4,  bp + 4);                      \
        cpa16((sb) + (krB * 128 + cBB * 16 + 8) * 4,  bp + 8);                      \
        cpa16((sb) + (krB * 128 + cBB * 16 + 12) * 4, bp + 12);                     \
    }

    ISSUE(0, sa0, sb0);
    asm volatile("cp.async.commit_group;" ::: "memory");

    for (int s = 0; s < 72; s++) {
        if (s < 71) {
            if ((s + 1) & 1) { ISSUE(s + 1, sa1, sb1); }
            else             { ISSUE(s + 1, sa0, sb0); }
        }
        asm volatile("cp.async.commit_group;" ::: "memory");
        asm volatile("cp.async.wait_group 1;" ::: "memory");
        __syncthreads();

        const float* Ab = (s & 1) ? &As[1][0] : &As[0][0];
        const float* Bb = (s & 1) ? &Bs[1][0] : &Bs[0][0];
#pragma unroll 16
        for (int kk = 0; kk < 32; kk++) {
            const ulonglong2* A2 = (const ulonglong2*)(Ab + kk * 128 + ty * 8);
            ulonglong2 ua0 = A2[0];
            ulonglong2 ua1 = A2[1];
            ull ap[4] = {ua0.x, ua0.y, ua1.x, ua1.y};
            float4 b0 = *(const float4*)(Bb + kk * 128 + tx * 4);
            float4 b1 = *(const float4*)(Bb + kk * 128 + 64 + tx * 4);
            ull bd[8] = {dup2(b0.x), dup2(b0.y), dup2(b0.z), dup2(b0.w),
                         dup2(b1.x), dup2(b1.y), dup2(b1.z), dup2(b1.w)};
#pragma unroll
            for (int i = 0; i < 4; i++)
#pragma unroll
                for (int j = 0; j < 8; j++)
                    acc[i][j] = fma2(ap[i], bd[j], acc[i][j]);
        }
        __syncthreads();
    }
#undef ISSUE

    // ---- epilogue: float2 stores (pairs along M)
    int mbase = pos0 + (ty << 3);
#pragma unroll
    for (int j = 0; j < 8; j++) {
        int oc = noff + ((j < 4) ? (4 * tx + j) : (64 + 4 * tx + (j - 4)));
        float* ob = out + (size_t)(b * COUT + oc) * HWSZ + mbase;
#pragma unroll
        for (int i2 = 0; i2 < 4; i2++) {
            float2 v = upk2(acc[i2][j]);
            *(float2*)(ob + i2 * 2) = v;
        }
    }
}

// ---------------- launch ----------------------------------------------------
extern "C" void kernel_launch(void* const* d_in, const int* in_sizes, int n_in,
                              void* d_out, int out_size) {
    const float* x        = (const float*)d_in[0];
    const float* offset_w = (const float*)d_in[1];
    const float* offset_b = (const float*)d_in[2];
    const float* mod_w    = (const float*)d_in[3];
    const float* mod_b    = (const float*)d_in[4];
    const float* reg_w    = (const float*)d_in[5];
    float* out = (float*)d_out;

    k_transpose<<<dim3(128, 8, 8), dim3(32, 8)>>>(x);
    k_wt<<<(KTOT * COUT + 255) / 256, 256>>>(reg_w);
    k_wom<<<(KTOT * 32 + 255) / 256, 256>>>(offset_w, mod_w);
    k_offmod<<<512, 128>>>(offset_b, mod_b);
    k_gather<<<1024, 256>>>();
    k_main<<<dim3(256, 2), 256>>>(out);
}

// round 11
// speedup vs baseline: 1.2803x; 1.2803x over previous
#include <cuda_runtime.h>
#include <cuda_bf16.h>
#include <cstdint>

#define HH 64
#define WW 64
#define CIN 256
#define COUT 256
#define BB 8
#define KKT 9
#define HWSZ 4096
#define KTOT 2304

typedef unsigned long long ull;

// ---------------- scratch ----------------------------------------------------
__device__ float  g_xn[BB * HWSZ * CIN];
__device__ float  g_wB[KTOT * 32];
__device__ short4 g_sxy[BB * KKT * HWSZ];
__device__ float4 g_swt[BB * KKT * HWSZ];
__device__ __nv_bfloat16 g_Ah[(size_t)BB * KKT * HWSZ * CIN];   // im2col hi
__device__ __nv_bfloat16 g_Al[(size_t)BB * KKT * HWSZ * CIN];   // im2col lo
__device__ __nv_bfloat16 g_wNh[COUT * KTOT];                    // W hi [oc][k]
__device__ __nv_bfloat16 g_wNl[COUT * KTOT];                    // W lo [oc][k]

// ---------------- helpers ----------------------------------------------------
__device__ __forceinline__ ull fma2(ull a, ull b, ull c) {
    ull d; asm("fma.rn.f32x2 %0, %1, %2, %3;" : "=l"(d) : "l"(a), "l"(b), "l"(c)); return d;
}
__device__ __forceinline__ float2 upk2(ull v) {
    float2 r; asm("mov.b64 {%0, %1}, %2;" : "=f"(r.x), "=f"(r.y) : "l"(v)); return r;
}
__device__ __forceinline__ ull dup2(float v) {
    ull r; asm("mov.b64 %0, {%1, %1};" : "=l"(r) : "f"(v)); return r;
}
__device__ __forceinline__ void cpa16(unsigned int s, const void* g) {
    asm volatile("cp.async.cg.shared.global [%0], [%1], 16;" :: "r"(s), "l"(g));
}
__device__ __forceinline__ uint32_t smem_u32(const void* p) {
    uint32_t a;
    asm("{ .reg .u64 t; cvta.to.shared.u64 t, %1; cvt.u32.u64 %0, t; }" : "=r"(a) : "l"(p));
    return a;
}
#define LDM4(d, a) \
    asm volatile("ldmatrix.sync.aligned.m8n8.x4.shared.b16 {%0,%1,%2,%3}, [%4];" \
                 : "=r"((d)[0]), "=r"((d)[1]), "=r"((d)[2]), "=r"((d)[3]) : "r"(a))
__device__ __forceinline__ void mma16816(float* c, const uint32_t* a,
                                         uint32_t b0, uint32_t b1) {
    asm volatile("mma.sync.aligned.m16n8k16.row.col.f32.bf16.bf16.f32 "
                 "{%0,%1,%2,%3}, {%4,%5,%6,%7}, {%8,%9}, {%0,%1,%2,%3};"
                 : "+f"(c[0]), "+f"(c[1]), "+f"(c[2]), "+f"(c[3])
                 : "r"(a[0]), "r"(a[1]), "r"(a[2]), "r"(a[3]), "r"(b0), "r"(b1));
}

// ---------------- k_transpose: NCHW -> NHWC --------------------------------
__global__ void k_transpose(const float* __restrict__ x) {
    __shared__ float tile[32][33];
    int b = blockIdx.z, p0 = blockIdx.x * 32, c0 = blockIdx.y * 32;
    const float* xb = x + (size_t)b * (CIN * HWSZ);
    float* ob = g_xn + (size_t)b * (HWSZ * CIN);
    int tx = threadIdx.x, ty = threadIdx.y;
#pragma unroll
    for (int i = 0; i < 4; i++)
        tile[ty + i * 8][tx] = xb[(size_t)(c0 + ty + i * 8) * HWSZ + p0 + tx];
    __syncthreads();
#pragma unroll
    for (int i = 0; i < 4; i++)
        ob[(size_t)(p0 + ty + i * 8) * CIN + c0 + tx] = tile[tx][ty + i * 8];
}

// ---------------- k_wN: reg_w -> hi/lo bf16 [oc][k] ------------------------
__global__ void k_wN(const float* __restrict__ reg_w) {
    int idx = blockIdx.x * 256 + threadIdx.x;
    if (idx >= COUT * KTOT) return;
    int oc = idx / KTOT, k = idx - oc * KTOT;
    int tap = k >> 8, c = k & 255;
    float w = reg_w[((size_t)oc * CIN + c) * KKT + tap];
    __nv_bfloat16 h = __float2bfloat16(w);
    g_wNh[idx] = h;
    g_wNl[idx] = __float2bfloat16(w - __bfloat162float(h));
}

// ---------------- k_wom: offset/mod weights [k][32] ------------------------
__global__ void k_wom(const float* __restrict__ ow, const float* __restrict__ mw) {
    int idx = blockIdx.x * 256 + threadIdx.x;
    if (idx >= KTOT * 32) return;
    int n = idx & 31, k = idx >> 5, tap = k >> 8, c = k & 255;
    float v = 0.f;
    if (n < 18)      v = ow[(size_t)(n * CIN + c) * KKT + tap];
    else if (n < 27) v = mw[(size_t)((n - 18) * CIN + c) * KKT + tap];
    g_wB[idx] = v;
}

// ---------------- k_offmod: offset/mod conv GEMM + prep (proven) -----------
__global__ void __launch_bounds__(128) k_offmod(const float* __restrict__ off_b,
                                                const float* __restrict__ mod_b) {
    __shared__ __align__(16) float As[32 * 64];
    __shared__ __align__(16) float Bs[32 * 32];
    __shared__ float red[64][28];
    int blk = blockIdx.x, b = blk >> 6, y = blk & 63, pos0 = y << 6;
    int tid = threadIdx.x, tx = tid & 7, ty = tid >> 3;
    int px = tid >> 2, cs2 = tid & 3, rB = tid >> 3, nB = (tid & 7) * 4;
    const float4* X4 = (const float4*)g_xn;

    ull acc[2][4];
#pragma unroll
    for (int i = 0; i < 2; i++)
#pragma unroll
        for (int j = 0; j < 4; j++) acc[i][j] = 0ULL;
    float4 ra[2][2], rb[2];

#define LOADSTAGE(s)                                                             \
    {                                                                            \
        int tap = (s) >> 3, cc = (s) & 7;                                        \
        int dy = tap / 3 - 1, dx = tap % 3 - 1;                                  \
        int y2 = y + dy;                                                         \
        bool rowok = (y2 >= 0) && (y2 < HH);                                     \
        _Pragma("unroll")                                                        \
        for (int it = 0; it < 2; it++) {                                         \
            int m = px + it * 32;                                                \
            int x2 = m + dx;                                                     \
            bool valid = rowok && (x2 >= 0) && (x2 < WW);                        \
            const float4* p = X4 + (size_t)(b * HWSZ + y2 * WW + x2) * 64        \
                                  + cc * 8 + cs2;                                \
            ra[it][0] = valid ? p[0] : make_float4(0.f, 0.f, 0.f, 0.f);          \
            ra[it][1] = valid ? p[4] : make_float4(0.f, 0.f, 0.f, 0.f);          \
        }                                                                        \
        rb[0] = *(const float4*)(g_wB + ((size_t)(s) * 32 + rB) * 32 + nB);      \
        rb[1] = *(const float4*)(g_wB + ((size_t)(s) * 32 + rB + 16) * 32 + nB); \
    }

    LOADSTAGE(0);
    for (int s = 0; s < 72; s++) {
        __syncthreads();
#pragma unroll
        for (int it = 0; it < 2; it++) {
            int col = (px + it * 32) ^ (cs2 << 3);
#pragma unroll
            for (int h = 0; h < 2; h++) {
                int kr = cs2 * 4 + h * 16;
                As[(kr + 0) * 64 + col] = (&ra[it][h].x)[0];
                As[(kr + 1) * 64 + col] = (&ra[it][h].x)[1];
                As[(kr + 2) * 64 + col] = (&ra[it][h].x)[2];
                As[(kr + 3) * 64 + col] = (&ra[it][h].x)[3];
            }
        }
        *(float4*)(Bs + rB * 32 + nB)        = rb[0];
        *(float4*)(Bs + (rB + 16) * 32 + nB) = rb[1];
        __syncthreads();
        if (s + 1 < 72) { LOADSTAGE(s + 1); }
#pragma unroll
        for (int kk = 0; kk < 32; kk++) {
            ulonglong2 a2 = *(const ulonglong2*)&As[kk * 64 + ((ty * 4) ^ ((kk & 12) << 1))];
            float4 bv = *(const float4*)&Bs[kk * 32 + tx * 4];
            ull bd[4] = {dup2(bv.x), dup2(bv.y), dup2(bv.z), dup2(bv.w)};
#pragma unroll
            for (int j = 0; j < 4; j++) {
                acc[0][j] = fma2(a2.x, bd[j], acc[0][j]);
                acc[1][j] = fma2(a2.y, bd[j], acc[1][j]);
            }
        }
    }
#undef LOADSTAGE

    __syncthreads();
#pragma unroll
    for (int i = 0; i < 2; i++)
#pragma unroll
        for (int j = 0; j < 4; j++) {
            int n = tx * 4 + j;
            if (n < 27) {
                float2 v = upk2(acc[i][j]);
                red[ty * 4 + 2 * i][n]     = v.x;
                red[ty * 4 + 2 * i + 1][n] = v.y;
            }
        }
    __syncthreads();

    for (int w = tid; w < 64 * 9; w += 128) {
        int px_i = w / 9, tap = w - px_i * 9, p2 = pos0 + px_i;
        float ay = red[px_i][2 * tap]     + off_b[2 * tap];
        float ax = red[px_i][2 * tap + 1] + off_b[2 * tap + 1];
        float am = red[px_i][18 + tap]    + mod_b[tap];
        float dyo = fminf(fmaxf(ay, -16.f), 16.f);
        float dxo = fminf(fmaxf(ax, -16.f), 16.f);
        float m = 1.f / (1.f + __expf(-am));
        float py  = dyo + (float)(tap / 3) + (float)y    - 1.f;
        float pxf = dxo + (float)(tap % 3) + (float)px_i - 1.f;
        float y0f = floorf(py), x0f = floorf(pxf);
        float ly = py - y0f, lx = pxf - x0f;
        int y0 = (int)y0f, x0 = (int)x0f;
        bool vy0 = (y0 >= 0) && (y0 < HH);
        bool vy1 = (y0 + 1 >= 0) && (y0 + 1 < HH);
        bool vx0 = (x0 >= 0) && (x0 < WW);
        bool vx1 = (x0 + 1 >= 0) && (x0 + 1 < WW);
        float w00 = (1.f - ly) * (1.f - lx) * m * ((vy0 && vx0) ? 1.f : 0.f);
        float w01 = (1.f - ly) * lx         * m * ((vy0 && vx1) ? 1.f : 0.f);
        float w10 = ly * (1.f - lx)         * m * ((vy1 && vx0) ? 1.f : 0.f);
        float w11 = ly * lx                 * m * ((vy1 && vx1) ? 1.f : 0.f);
        int y0c = min(max(y0, 0), HH - 1), y1c = min(max(y0 + 1, 0), HH - 1);
        int x0c = min(max(x0, 0), WW - 1), x1c = min(max(x0 + 1, 0), WW - 1);
        int si = (b * 9 + tap) * HWSZ + p2;
        g_sxy[si] = make_short4((short)y0c, (short)y1c, (short)x0c, (short)x1c);
        g_swt[si] = make_float4(w00, w01, w10, w11);
    }
}

// ---------------- k_gather: bilinear -> hi/lo bf16 im2col ------------------
__global__ void __launch_bounds__(256) k_gather() {
    int blk = blockIdx.x, b = blk >> 7, p32 = blk & 127, pos0 = p32 << 5;
    int tid = threadIdx.x, px = tid >> 3, cs = tid & 7;
    int pb = b * HWSZ;
    const float4* X4 = (const float4*)g_xn;

    for (int tap = 0; tap < 9; tap++) {
        int bt = b * 9 + tap;
        int si = bt * HWSZ + pos0 + px;
        short4 s = g_sxy[si];
        float4 wc = g_swt[si];
        int a00 = (pb + s.x * WW + s.z) << 6;
        int a01 = (pb + s.x * WW + s.w) << 6;
        int a10 = (pb + s.y * WW + s.z) << 6;
        int a11 = (pb + s.y * WW + s.w) << 6;
        size_t rowb = ((size_t)bt * HWSZ + pos0 + px) * 256;

#pragma unroll
        for (int i = 0; i < 8; i++) {
            int c4 = i * 8 + cs;
            float4 v0 = X4[a00 + c4];
            float4 v1 = X4[a01 + c4];
            float4 v2 = X4[a10 + c4];
            float4 v3 = X4[a11 + c4];
            float f0 = wc.x * v0.x + wc.y * v1.x + wc.z * v2.x + wc.w * v3.x;
            float f1 = wc.x * v0.y + wc.y * v1.y + wc.z * v2.y + wc.w * v3.y;
            float f2 = wc.x * v0.z + wc.y * v1.z + wc.z * v2.z + wc.w * v3.z;
            float f3 = wc.x * v0.w + wc.y * v1.w + wc.z * v2.w + wc.w * v3.w;
            __nv_bfloat16 h0 = __float2bfloat16(f0), h1 = __float2bfloat16(f1);
            __nv_bfloat16 h2 = __float2bfloat16(f2), h3 = __float2bfloat16(f3);
            __nv_bfloat162 th0 = __halves2bfloat162(h0, h1);
            __nv_bfloat162 th1 = __halves2bfloat162(h2, h3);
            __nv_bfloat162 tl0 = __halves2bfloat162(
                __float2bfloat16(f0 - __bfloat162float(h0)),
                __float2bfloat16(f1 - __bfloat162float(h1)));
            __nv_bfloat162 tl1 = __halves2bfloat162(
                __float2bfloat16(f2 - __bfloat162float(h2)),
                __float2bfloat16(f3 - __bfloat162float(h3)));
            uint2 uh, ulv;
            uh.x = *(unsigned*)&th0;  uh.y = *(unsigned*)&th1;
            ulv.x = *(unsigned*)&tl0; ulv.y = *(unsigned*)&tl1;
            *(uint2*)(g_Ah + rowb + c4 * 4) = uh;
            *(uint2*)(g_Al + rowb + c4 * 4) = ulv;
        }
    }
}

// ---------------- k_main: HMMA split-bf16 GEMM -----------------------------
// grid (256, 2): M=128 (pos), N=128 (oc half). K=2304 = 36 stages of 64.
// smem rows padded to 144 B (9 granules) -> ldmatrix + cp.async conflict-free.
// 8 warps: 4 along M (32 rows) x 2 along N (64 cols). 3-pass split bf16.
#define RSTR 144
#define ATILE (128 * RSTR)            // 18432
#define BUFSZ (4 * ATILE)             // 73728
__global__ void __launch_bounds__(256, 1) k_main(float* __restrict__ out) {
    extern __shared__ __align__(16) char smem[];
    uint32_t sb = smem_u32(smem);
    int tid = threadIdx.x, wid = tid >> 5, lid = tid & 31;
    int mb = blockIdx.x, b = mb >> 5, pos0 = (mb & 31) << 7;
    int noff = blockIdx.y << 7;

    int r = tid >> 3, g = tid & 7;
    int wm = (wid >> 1) * 32, wn = (wid & 1) * 64;
    int lrow = (lid & 7) + ((lid >> 3) & 1) * 8;
    uint32_t lcol = ((lid >> 4) & 1) * 16;
    uint32_t aBase = (uint32_t)(wm + lrow) * RSTR + lcol;
    uint32_t bBase = (uint32_t)(wn + lrow) * RSTR + lcol;

    float acc[2][8][4];
#pragma unroll
    for (int i = 0; i < 2; i++)
#pragma unroll
        for (int j = 0; j < 8; j++)
#pragma unroll
            for (int q = 0; q < 4; q++) acc[i][j][q] = 0.f;

#define FILLST(s_)                                                                   \
    {                                                                                \
        uint32_t bb = sb + ((s_) & 1) * BUFSZ;                                       \
        int tap = (s_) >> 2;                                                         \
        int c0 = ((s_) & 3) << 6;                                                    \
        size_t arow = (size_t)(b * 9 + tap) * HWSZ + pos0;                           \
        _Pragma("unroll")                                                            \
        for (int q = 0; q < 4; q++) {                                                \
            int rr = r + 32 * q;                                                     \
            uint32_t d = bb + rr * RSTR + g * 16;                                    \
            cpa16(d,             g_Ah + (arow + rr) * 256 + c0 + g * 8);             \
            cpa16(d + ATILE,     g_Al + (arow + rr) * 256 + c0 + g * 8);             \
            cpa16(d + 2 * ATILE, g_wNh + (size_t)(noff + rr) * KTOT + (s_) * 64 + g * 8); \
            cpa16(d + 3 * ATILE, g_wNl + (size_t)(noff + rr) * KTOT + (s_) * 64 + g * 8); \
        }                                                                            \
        asm volatile("cp.async.commit_group;" ::: "memory");                         \
    }

    FILLST(0);
    for (int s = 0; s < 36; s++) {
        if (s < 35) { FILLST(s + 1); }
        asm volatile("cp.async.commit_group;" ::: "memory");
        asm volatile("cp.async.wait_group 1;" ::: "memory");
        __syncthreads();

        uint32_t bufA  = sb + (s & 1) * BUFSZ;
        uint32_t bufAl = bufA + ATILE;
        uint32_t bufB  = bufA + 2 * ATILE;
        uint32_t bufBl = bufA + 3 * ATILE;
#pragma unroll
        for (int ks = 0; ks < 4; ks++) {
            uint32_t ko = ks * 32;
            uint32_t ah[2][4], al[2][4], bh[4][4], bl[4][4];
#pragma unroll
            for (int mt = 0; mt < 2; mt++) {
                LDM4(ah[mt], bufA  + aBase + mt * (16 * RSTR) + ko);
                LDM4(al[mt], bufAl + aBase + mt * (16 * RSTR) + ko);
            }
#pragma unroll
            for (int nt = 0; nt < 4; nt++) {
                LDM4(bh[nt], bufB  + bBase + nt * (16 * RSTR) + ko);
                LDM4(bl[nt], bufBl + bBase + nt * (16 * RSTR) + ko);
            }
#pragma unroll
            for (int mt = 0; mt < 2; mt++)
#pragma unroll
                for (int n8 = 0; n8 < 8; n8++) {
                    int nt = n8 >> 1, h = n8 & 1;
                    mma16816(acc[mt][n8], ah[mt], bh[nt][h], bh[nt][h + 2]);
                    mma16816(acc[mt][n8], ah[mt], bl[nt][h], bl[nt][h + 2]);
                    mma16816(acc[mt][n8], al[mt], bh[nt][h], bh[nt][h + 2]);
                }
        }
        __syncthreads();
    }
#undef FILLST

    // epilogue: direct stores. c0:(m,n) c1:(m,n+1) c2:(m+8,n) c3:(m+8,n+1)
    int mrow = lid >> 2, ncol = (lid & 3) * 2;
#pragma unroll
    for (int mt = 0; mt < 2; mt++)
#pragma unroll
        for (int n8 = 0; n8 < 8; n8++) {
            int m = pos0 + wm + mt * 16 + mrow;
            int n = noff + wn + n8 * 8 + ncol;
            float* o0 = out + (size_t)(b * COUT + n) * HWSZ + m;
            float* o1 = o0 + HWSZ;
            o0[0] = acc[mt][n8][0];
            o1[0] = acc[mt][n8][1];
            o0[8] = acc[mt][n8][2];
            o1[8] = acc[mt][n8][3];
        }
}

// ---------------- launch ----------------------------------------------------
extern "C" void kernel_launch(void* const* d_in, const int* in_sizes, int n_in,
                              void* d_out, int out_size) {
    const float* x        = (const float*)d_in[0];
    const float* offset_w = (const float*)d_in[1];
    const float* offset_b = (const float*)d_in[2];
    const float* mod_w    = (const float*)d_in[3];
    const float* mod_b    = (const float*)d_in[4];
    const float* reg_w    = (const float*)d_in[5];
    float* out = (float*)d_out;

    cudaFuncSetAttribute(k_main, cudaFuncAttributeMaxDynamicSharedMemorySize,
                         2 * BUFSZ);

    k_transpose<<<dim3(128, 8, 8), dim3(32, 8)>>>(x);
    k_wN<<<(COUT * KTOT + 255) / 256, 256>>>(reg_w);
    k_wom<<<(KTOT * 32 + 255) / 256, 256>>>(offset_w, mod_w);
    k_offmod<<<512, 128>>>(offset_b, mod_b);
    k_gather<<<1024, 256>>>();
    k_main<<<dim3(256, 2), 256, 2 * BUFSZ>>>(out);
}

// round 14
// speedup vs baseline: 1.4825x; 1.1579x over previous
#include <cuda_runtime.h>
#include <cuda_bf16.h>
#include <cstdint>

#define HH 64
#define WW 64
#define CIN 256
#define COUT 256
#define BB 8
#define KKT 9
#define HWSZ 4096
#define KTOT 2304

typedef unsigned long long ull;

// ---------------- scratch ----------------------------------------------------
__device__ float  g_xn[BB * HWSZ * CIN];
__device__ float  g_wB[KTOT * 32];
__device__ short4 g_sxy[BB * KKT * HWSZ];
__device__ float4 g_swt[BB * KKT * HWSZ];
__device__ __nv_bfloat16 g_Ah[(size_t)BB * KKT * HWSZ * CIN];   // im2col hi
__device__ __nv_bfloat16 g_Al[(size_t)BB * KKT * HWSZ * CIN];   // im2col lo
__device__ __nv_bfloat16 g_wNh[COUT * KTOT];                    // W hi [oc][k]
__device__ __nv_bfloat16 g_wNl[COUT * KTOT];                    // W lo [oc][k]

// ---------------- helpers ----------------------------------------------------
__device__ __forceinline__ ull fma2(ull a, ull b, ull c) {
    ull d; asm("fma.rn.f32x2 %0, %1, %2, %3;" : "=l"(d) : "l"(a), "l"(b), "l"(c)); return d;
}
__device__ __forceinline__ float2 upk2(ull v) {
    float2 r; asm("mov.b64 {%0, %1}, %2;" : "=f"(r.x), "=f"(r.y) : "l"(v)); return r;
}
__device__ __forceinline__ ull dup2(float v) {
    ull r; asm("mov.b64 %0, {%1, %1};" : "=l"(r) : "f"(v)); return r;
}
__device__ __forceinline__ void cpa16(unsigned int s, const void* g) {
    asm volatile("cp.async.cg.shared.global [%0], [%1], 16;" :: "r"(s), "l"(g));
}
__device__ __forceinline__ uint32_t smem_u32(const void* p) {
    uint32_t a;
    asm("{ .reg .u64 t; cvta.to.shared.u64 t, %1; cvt.u32.u64 %0, t; }" : "=r"(a) : "l"(p));
    return a;
}
#define LDM4(d, a) \
    asm volatile("ldmatrix.sync.aligned.m8n8.x4.shared.b16 {%0,%1,%2,%3}, [%4];" \
                 : "=r"((d)[0]), "=r"((d)[1]), "=r"((d)[2]), "=r"((d)[3]) : "r"(a))
__device__ __forceinline__ void mma16816(float* c, const uint32_t* a,
                                         uint32_t b0, uint32_t b1) {
    asm volatile("mma.sync.aligned.m16n8k16.row.col.f32.bf16.bf16.f32 "
                 "{%0,%1,%2,%3}, {%4,%5,%6,%7}, {%8,%9}, {%0,%1,%2,%3};"
                 : "+f"(c[0]), "+f"(c[1]), "+f"(c[2]), "+f"(c[3])
                 : "r"(a[0]), "r"(a[1]), "r"(a[2]), "r"(a[3]), "r"(b0), "r"(b1));
}

// ---------------- k_transpose: NCHW -> NHWC --------------------------------
__global__ void k_transpose(const float* __restrict__ x) {
    __shared__ float tile[32][33];
    int b = blockIdx.z, p0 = blockIdx.x * 32, c0 = blockIdx.y * 32;
    const float* xb = x + (size_t)b * (CIN * HWSZ);
    float* ob = g_xn + (size_t)b * (HWSZ * CIN);
    int tx = threadIdx.x, ty = threadIdx.y;
#pragma unroll
    for (int i = 0; i < 4; i++)
        tile[ty + i * 8][tx] = xb[(size_t)(c0 + ty + i * 8) * HWSZ + p0 + tx];
    __syncthreads();
#pragma unroll
    for (int i = 0; i < 4; i++)
        ob[(size_t)(p0 + ty + i * 8) * CIN + c0 + tx] = tile[tx][ty + i * 8];
}

// ---------------- k_wN: reg_w -> hi/lo bf16 [oc][k] ------------------------
__global__ void k_wN(const float* __restrict__ reg_w) {
    int idx = blockIdx.x * 256 + threadIdx.x;
    if (idx >= COUT * KTOT) return;
    int oc = idx / KTOT, k = idx - oc * KTOT;
    int tap = k >> 8, c = k & 255;
    float w = reg_w[((size_t)oc * CIN + c) * KKT + tap];
    __nv_bfloat16 h = __float2bfloat16(w);
    g_wNh[idx] = h;
    g_wNl[idx] = __float2bfloat16(w - __bfloat162float(h));
}

// ---------------- k_wom: offset/mod weights [k][32] ------------------------
__global__ void k_wom(const float* __restrict__ ow, const float* __restrict__ mw) {
    int idx = blockIdx.x * 256 + threadIdx.x;
    if (idx >= KTOT * 32) return;
    int n = idx & 31, k = idx >> 5, tap = k >> 8, c = k & 255;
    float v = 0.f;
    if (n < 18)      v = ow[(size_t)(n * CIN + c) * KKT + tap];
    else if (n < 27) v = mw[(size_t)((n - 18) * CIN + c) * KKT + tap];
    g_wB[idx] = v;
}

// ---------------- k_offmod: offset/mod conv GEMM + prep (proven) -----------
__global__ void __launch_bounds__(128) k_offmod(const float* __restrict__ off_b,
                                                const float* __restrict__ mod_b) {
    __shared__ __align__(16) float As[32 * 64];
    __shared__ __align__(16) float Bs[32 * 32];
    __shared__ float red[64][28];
    int blk = blockIdx.x, b = blk >> 6, y = blk & 63, pos0 = y << 6;
    int tid = threadIdx.x, tx = tid & 7, ty = tid >> 3;
    int px = tid >> 2, cs2 = tid & 3, rB = tid >> 3, nB = (tid & 7) * 4;
    const float4* X4 = (const float4*)g_xn;

    ull acc[2][4];
#pragma unroll
    for (int i = 0; i < 2; i++)
#pragma unroll
        for (int j = 0; j < 4; j++) acc[i][j] = 0ULL;
    float4 ra[2][2], rb[2];

#define LOADSTAGE(s)                                                             \
    {                                                                            \
        int tap = (s) >> 3, cc = (s) & 7;                                        \
        int dy = tap / 3 - 1, dx = tap % 3 - 1;                                  \
        int y2 = y + dy;                                                         \
        bool rowok = (y2 >= 0) && (y2 < HH);                                     \
        _Pragma("unroll")                                                        \
        for (int it = 0; it < 2; it++) {                                         \
            int m = px + it * 32;                                                \
            int x2 = m + dx;                                                     \
            bool valid = rowok && (x2 >= 0) && (x2 < WW);                        \
            const float4* p = X4 + (size_t)(b * HWSZ + y2 * WW + x2) * 64        \
                                  + cc * 8 + cs2;                                \
            ra[it][0] = valid ? p[0] : make_float4(0.f, 0.f, 0.f, 0.f);          \
            ra[it][1] = valid ? p[4] : make_float4(0.f, 0.f, 0.f, 0.f);          \
        }                                                                        \
        rb[0] = *(const float4*)(g_wB + ((size_t)(s) * 32 + rB) * 32 + nB);      \
        rb[1] = *(const float4*)(g_wB + ((size_t)(s) * 32 + rB + 16) * 32 + nB); \
    }

    LOADSTAGE(0);
    for (int s = 0; s < 72; s++) {
        __syncthreads();
#pragma unroll
        for (int it = 0; it < 2; it++) {
            int col = (px + it * 32) ^ (cs2 << 3);
#pragma unroll
            for (int h = 0; h < 2; h++) {
                int kr = cs2 * 4 + h * 16;
                As[(kr + 0) * 64 + col] = (&ra[it][h].x)[0];
                As[(kr + 1) * 64 + col] = (&ra[it][h].x)[1];
                As[(kr + 2) * 64 + col] = (&ra[it][h].x)[2];
                As[(kr + 3) * 64 + col] = (&ra[it][h].x)[3];
            }
        }
        *(float4*)(Bs + rB * 32 + nB)        = rb[0];
        *(float4*)(Bs + (rB + 16) * 32 + nB) = rb[1];
        __syncthreads();
        if (s + 1 < 72) { LOADSTAGE(s + 1); }
#pragma unroll
        for (int kk = 0; kk < 32; kk++) {
            ulonglong2 a2 = *(const ulonglong2*)&As[kk * 64 + ((ty * 4) ^ ((kk & 12) << 1))];
            float4 bv = *(const float4*)&Bs[kk * 32 + tx * 4];
            ull bd[4] = {dup2(bv.x), dup2(bv.y), dup2(bv.z), dup2(bv.w)};
#pragma unroll
            for (int j = 0; j < 4; j++) {
                acc[0][j] = fma2(a2.x, bd[j], acc[0][j]);
                acc[1][j] = fma2(a2.y, bd[j], acc[1][j]);
            }
        }
    }
#undef LOADSTAGE

    __syncthreads();
#pragma unroll
    for (int i = 0; i < 2; i++)
#pragma unroll
        for (int j = 0; j < 4; j++) {
            int n = tx * 4 + j;
            if (n < 27) {
                float2 v = upk2(acc[i][j]);
                red[ty * 4 + 2 * i][n]     = v.x;
                red[ty * 4 + 2 * i + 1][n] = v.y;
            }
        }
    __syncthreads();

    for (int w = tid; w < 64 * 9; w += 128) {
        int px_i = w / 9, tap = w - px_i * 9, p2 = pos0 + px_i;
        float ay = red[px_i][2 * tap]     + off_b[2 * tap];
        float ax = red[px_i][2 * tap + 1] + off_b[2 * tap + 1];
        float am = red[px_i][18 + tap]    + mod_b[tap];
        float dyo = fminf(fmaxf(ay, -16.f), 16.f);
        float dxo = fminf(fmaxf(ax, -16.f), 16.f);
        float m = 1.f / (1.f + __expf(-am));
        float py  = dyo + (float)(tap / 3) + (float)y    - 1.f;
        float pxf = dxo + (float)(tap % 3) + (float)px_i - 1.f;
        float y0f = floorf(py), x0f = floorf(pxf);
        float ly = py - y0f, lx = pxf - x0f;
        int y0 = (int)y0f, x0 = (int)x0f;
        bool vy0 = (y0 >= 0) && (y0 < HH);
        bool vy1 = (y0 + 1 >= 0) && (y0 + 1 < HH);
        bool vx0 = (x0 >= 0) && (x0 < WW);
        bool vx1 = (x0 + 1 >= 0) && (x0 + 1 < WW);
        float w00 = (1.f - ly) * (1.f - lx) * m * ((vy0 && vx0) ? 1.f : 0.f);
        float w01 = (1.f - ly) * lx         * m * ((vy0 && vx1) ? 1.f : 0.f);
        float w10 = ly * (1.f - lx)         * m * ((vy1 && vx0) ? 1.f : 0.f);
        float w11 = ly * lx                 * m * ((vy1 && vx1) ? 1.f : 0.f);
        int y0c = min(max(y0, 0), HH - 1), y1c = min(max(y0 + 1, 0), HH - 1);
        int x0c = min(max(x0, 0), WW - 1), x1c = min(max(x0 + 1, 0), WW - 1);
        int si = (b * 9 + tap) * HWSZ + p2;
        g_sxy[si] = make_short4((short)y0c, (short)y1c, (short)x0c, (short)x1c);
        g_swt[si] = make_float4(w00, w01, w10, w11);
    }
}

// ---------------- k_gather: bilinear -> hi/lo bf16 im2col ------------------
__global__ void __launch_bounds__(256) k_gather() {
    int blk = blockIdx.x, b = blk >> 7, p32 = blk & 127, pos0 = p32 << 5;
    int tid = threadIdx.x, px = tid >> 3, cs = tid & 7;
    int pb = b * HWSZ;
    const float4* X4 = (const float4*)g_xn;

    for (int tap = 0; tap < 9; tap++) {
        int bt = b * 9 + tap;
        int si = bt * HWSZ + pos0 + px;
        short4 s = g_sxy[si];
        float4 wc = g_swt[si];
        int a00 = (pb + s.x * WW + s.z) << 6;
        int a01 = (pb + s.x * WW + s.w) << 6;
        int a10 = (pb + s.y * WW + s.z) << 6;
        int a11 = (pb + s.y * WW + s.w) << 6;
        size_t rowb = ((size_t)bt * HWSZ + pos0 + px) * 256;

#pragma unroll
        for (int i = 0; i < 8; i++) {
            int c4 = i * 8 + cs;
            float4 v0 = X4[a00 + c4];
            float4 v1 = X4[a01 + c4];
            float4 v2 = X4[a10 + c4];
            float4 v3 = X4[a11 + c4];
            float f0 = wc.x * v0.x + wc.y * v1.x + wc.z * v2.x + wc.w * v3.x;
            float f1 = wc.x * v0.y + wc.y * v1.y + wc.z * v2.y + wc.w * v3.y;
            float f2 = wc.x * v0.z + wc.y * v1.z + wc.z * v2.z + wc.w * v3.z;
            float f3 = wc.x * v0.w + wc.y * v1.w + wc.z * v2.w + wc.w * v3.w;
            __nv_bfloat16 h0 = __float2bfloat16(f0), h1 = __float2bfloat16(f1);
            __nv_bfloat16 h2 = __float2bfloat16(f2), h3 = __float2bfloat16(f3);
            __nv_bfloat162 th0 = __halves2bfloat162(h0, h1);
            __nv_bfloat162 th1 = __halves2bfloat162(h2, h3);
            __nv_bfloat162 tl0 = __halves2bfloat162(
                __float2bfloat16(f0 - __bfloat162float(h0)),
                __float2bfloat16(f1 - __bfloat162float(h1)));
            __nv_bfloat162 tl1 = __halves2bfloat162(
                __float2bfloat16(f2 - __bfloat162float(h2)),
                __float2bfloat16(f3 - __bfloat162float(h3)));
            uint2 uh, ulv;
            uh.x = *(unsigned*)&th0;  uh.y = *(unsigned*)&th1;
            ulv.x = *(unsigned*)&tl0; ulv.y = *(unsigned*)&tl1;
            *(uint2*)(g_Ah + rowb + c4 * 4) = uh;
            *(uint2*)(g_Al + rowb + c4 * 4) = ulv;
        }
    }
}

// ---------------- k_main: HMMA split-bf16 GEMM -----------------------------
// grid (2, 256): x = oc half (fast dim -> paired blocks share A tile in L2),
// y = (b, 128-px). K=2304 = 36 stages of 64, 3-stage cp.async ring (216 KB).
// smem rows padded to 144 B; 8 warps: 4 along M x 2 along N; 3-pass split bf16.
#define RSTR 144
#define ATILE (128 * RSTR)            // 18432
#define BUFSZ (4 * ATILE)             // 73728
#define NSTG 3
__global__ void __launch_bounds__(256, 1) k_main(float* __restrict__ out) {
    extern __shared__ __align__(16) char smem[];
    uint32_t sb = smem_u32(smem);
    int tid = threadIdx.x, wid = tid >> 5, lid = tid & 31;
    int mb = blockIdx.y, b = mb >> 5, pos0 = (mb & 31) << 7;
    int noff = blockIdx.x << 7;

    int r = tid >> 3, g = tid & 7;
    int wm = (wid >> 1) * 32, wn = (wid & 1) * 64;
    int lrow = (lid & 7) + ((lid >> 3) & 1) * 8;
    uint32_t lcol = ((lid >> 4) & 1) * 16;
    uint32_t aBase = (uint32_t)(wm + lrow) * RSTR + lcol;
    uint32_t bBase = (uint32_t)(wn + lrow) * RSTR + lcol;

    float acc[2][8][4];
#pragma unroll
    for (int i = 0; i < 2; i++)
#pragma unroll
        for (int j = 0; j < 8; j++)
#pragma unroll
            for (int q = 0; q < 4; q++) acc[i][j][q] = 0.f;

#define FILLST(s_)                                                                   \
    {                                                                                \
        uint32_t bb = sb + ((s_) % NSTG) * BUFSZ;                                    \
        int tap = (s_) >> 2;                                                         \
        int c0 = ((s_) & 3) << 6;                                                    \
        size_t arow = (size_t)(b * 9 + tap) * HWSZ + pos0;                           \
        _Pragma("unroll")                                                            \
        for (int q = 0; q < 4; q++) {                                                \
            int rr = r + 32 * q;                                                     \
            uint32_t d = bb + rr * RSTR + g * 16;                                    \
            cpa16(d,             g_Ah + (arow + rr) * 256 + c0 + g * 8);             \
            cpa16(d + ATILE,     g_Al + (arow + rr) * 256 + c0 + g * 8);             \
            cpa16(d + 2 * ATILE, g_wNh + (size_t)(noff + rr) * KTOT + (s_) * 64 + g * 8); \
            cpa16(d + 3 * ATILE, g_wNl + (size_t)(noff + rr) * KTOT + (s_) * 64 + g * 8); \
        }                                                                            \
        asm volatile("cp.async.commit_group;" ::: "memory");                         \
    }

    FILLST(0);
    FILLST(1);
    for (int s = 0; s < 36; s++) {
        if (s + 2 < 36) { FILLST(s + 2); }
        else { asm volatile("cp.async.commit_group;" ::: "memory"); }
        asm volatile("cp.async.wait_group 2;" ::: "memory");
        __syncthreads();

        uint32_t bufA  = sb + (s % NSTG) * BUFSZ;
        uint32_t bufAl = bufA + ATILE;
        uint32_t bufB  = bufA + 2 * ATILE;
        uint32_t bufBl = bufA + 3 * ATILE;
#pragma unroll
        for (int ks = 0; ks < 4; ks++) {
            uint32_t ko = ks * 32;
            uint32_t ah[2][4], al[2][4], bh[4][4], bl[4][4];
#pragma unroll
            for (int mt = 0; mt < 2; mt++) {
                LDM4(ah[mt], bufA  + aBase + mt * (16 * RSTR) + ko);
                LDM4(al[mt], bufAl + aBase + mt * (16 * RSTR) + ko);
            }
#pragma unroll
            for (int nt = 0; nt < 4; nt++) {
                LDM4(bh[nt], bufB  + bBase + nt * (16 * RSTR) + ko);
                LDM4(bl[nt], bufBl + bBase + nt * (16 * RSTR) + ko);
            }
#pragma unroll
            for (int mt = 0; mt < 2; mt++)
#pragma unroll
                for (int n8 = 0; n8 < 8; n8++) {
                    int nt = n8 >> 1, h = n8 & 1;
                    mma16816(acc[mt][n8], ah[mt], bh[nt][h], bh[nt][h + 2]);
                    mma16816(acc[mt][n8], ah[mt], bl[nt][h], bl[nt][h + 2]);
                    mma16816(acc[mt][n8], al[mt], bh[nt][h], bh[nt][h + 2]);
                }
        }
        __syncthreads();
    }
#undef FILLST

    // epilogue: c0:(m,n) c1:(m,n+1) c2:(m+8,n) c3:(m+8,n+1)
    int mrow = lid >> 2, ncol = (lid & 3) * 2;
#pragma unroll
    for (int mt = 0; mt < 2; mt++)
#pragma unroll
        for (int n8 = 0; n8 < 8; n8++) {
            int m = pos0 + wm + mt * 16 + mrow;
            int n = noff + wn + n8 * 8 + ncol;
            float* o0 = out + (size_t)(b * COUT + n) * HWSZ + m;
            float* o1 = o0 + HWSZ;
            o0[0] = acc[mt][n8][0];
            o1[0] = acc[mt][n8][1];
            o0[8] = acc[mt][n8][2];
            o1[8] = acc[mt][n8][3];
        }
}

// ---------------- launch ----------------------------------------------------
extern "C" void kernel_launch(void* const* d_in, const int* in_sizes, int n_in,
                              void* d_out, int out_size) {
    const float* x        = (const float*)d_in[0];
    const float* offset_w = (const float*)d_in[1];
    const float* offset_b = (const float*)d_in[2];
    const float* mod_w    = (const float*)d_in[3];
    const float* mod_b    = (const float*)d_in[4];
    const float* reg_w    = (const float*)d_in[5];
    float* out = (float*)d_out;

    cudaFuncSetAttribute(k_main, cudaFuncAttributeMaxDynamicSharedMemorySize,
                         NSTG * BUFSZ);

    k_transpose<<<dim3(128, 8, 8), dim3(32, 8)>>>(x);
    k_wN<<<(COUT * KTOT + 255) / 256, 256>>>(reg_w);
    k_wom<<<(KTOT * 32 + 255) / 256, 256>>>(offset_w, mod_w);
    k_offmod<<<512, 128>>>(offset_b, mod_b);
    k_gather<<<1024, 256>>>();
    k_main<<<dim3(2, 256), 256, NSTG * BUFSZ>>>(out);
}